// round 11
// baseline (speedup 1.0000x reference)
#include <cuda_runtime.h>
#include <cstdint>

#define NN 512
#define CC 64
#define RR 32
#define BT 64
#define NT 128

#define PC2(k) (((k) & 3) * 20 + ((k) >> 2))    // k<64, stride 80
// mma n-column for physical channel f (each thread owns 8 contiguous f)
#define PERMN(f) (((f) & 32) + ((((f) & 7) >> 1) << 3) + ((((f) >> 3) & 3) << 1) + ((f) & 1))

// smem layout (float units)
#define OFF_W1   0        // [64 n][36] tf32 (pc1)   | sPart overlay
#define OFF_W2   2304     // [64 n][80] tf32 (pc2)   |
#define OFF_H    7424     // [64 b][80] tf32 (rotated pc2)
#define SMEM_FLOATS 12544
#define SMEM_BYTES (SMEM_FLOATS * 4)   // 50176 B -> 3 CTAs/SM

// prep-repacked device buffers (fragment-coalesced layouts)
__device__ uint32_t g_rbf2[(size_t)NN * 2 * NN * 16];  // [(a*2+kt)*512+row][16] tf32
__device__ float    g_x0p[4 * NN * 16];                // [(t'*2+nh)*512+row][16]
__device__ float    g_x1p[12 * NN * 16];               // [(t*2+nh)*512+row][16]
__device__ float    g_up[(size_t)NN * NN * 4];         // [a*512+row][4] (xyz0)

extern __shared__ float smem[];

__device__ __forceinline__ uint32_t f2tf(float x) {
    uint32_t u;
    asm("cvt.rna.tf32.f32 %0, %1;" : "=r"(u) : "f"(x));
    return u;
}

__device__ __forceinline__ void mma_tf32(float c[4], uint32_t a0, uint32_t a1,
                                         uint32_t a2, uint32_t a3,
                                         uint32_t b0, uint32_t b1) {
    asm volatile(
        "mma.sync.aligned.m16n8k8.row.col.f32.tf32.tf32.f32 "
        "{%0,%1,%2,%3}, {%4,%5,%6,%7}, {%8,%9}, {%0,%1,%2,%3};"
        : "+f"(c[0]), "+f"(c[1]), "+f"(c[2]), "+f"(c[3])
        : "r"(a0), "r"(a1), "r"(a2), "r"(a3), "r"(b0), "r"(b1));
}

// ---- prep 1: rbf -> tf32 fragment-coalesced [(a*2+kt)*512+row][cpos*4+e] ----
// dst[cpos*4+e] = tf32(rbf[a][row][16*kt + 4*e + cpos])
__global__ void prep_rbf2_kernel(const float* __restrict__ grbf) {
    int idx  = blockIdx.x * 256 + threadIdx.x;     // 524288 = (a,row) pairs * 2 kt
    int kt   = idx & 1;
    int pair = idx >> 1;                           // a*512 + row
    const float* src = grbf + (size_t)pair * RR + kt * 16;
    uint32_t* dst = g_rbf2 + ((size_t)((pair >> 9) * 2 + kt) * NN + (pair & 511)) * 16;
    float s[16];
    #pragma unroll
    for (int j = 0; j < 4; j++)
        *(float4*)&s[j * 4] = ((const float4*)src)[j];
    #pragma unroll
    for (int cpos = 0; cpos < 4; cpos++)
        #pragma unroll
        for (int e = 0; e < 4; e++)
            dst[cpos * 4 + e] = f2tf(s[4 * e + cpos]);
}

// ---- prep 2: u padding + x0/x1 fragment repack ----
__global__ void prep_misc_kernel(const float* __restrict__ gx0,
                                 const float* __restrict__ gx1,
                                 const float* __restrict__ gu) {
    int idx = blockIdx.x * 256 + threadIdx.x;      // 262144 + 8192 = 270336
    if (idx < NN * NN) {
        const float* s = gu + (size_t)idx * 3;
        float4 v = make_float4(s[0], s[1], s[2], 0.f);
        *(float4*)&g_up[(size_t)idx * 4] = v;
    } else {
        int j = idx - NN * NN;                     // j < 8192 = 16 slots * 512 rows
        int slot = j >> 9, row = j & 511;
        if (slot < 4) {        // x0p: slot = t'*2 + nh
            int tp = slot >> 1, nh = slot & 1;
            float* d = g_x0p + ((size_t)slot * NN + row) * 16;
            #pragma unroll
            for (int cpos = 0; cpos < 4; cpos++)
                #pragma unroll
                for (int e = 0; e < 4; e++)
                    d[cpos * 4 + e] = gx0[row * 64 + nh * 32 + cpos * 8 + tp * 4 + e];
        } else {               // x1p: slot-4 = t*2 + nh
            int t = (slot - 4) >> 1, nh = (slot - 4) & 1;
            float* d = g_x1p + ((size_t)(slot - 4) * NN + row) * 16;
            #pragma unroll
            for (int cpos = 0; cpos < 4; cpos++)
                #pragma unroll
                for (int e = 0; e < 4; e++)
                    d[cpos * 4 + e] = gx1[row * 192 + nh * 96 + cpos * 24 + t * 4 + e];
        }
    }
}

__global__ __launch_bounds__(NT, 3)
void conv_tfn_tc6_kernel(const float* __restrict__ gw1,
                         const float* __restrict__ gb1,
                         const float* __restrict__ gw2,
                         const float* __restrict__ gb2,
                         float* __restrict__ out)
{
    const int a    = blockIdx.x;
    const int m    = blockIdx.y;
    const int tid  = threadIdx.x;
    const int w    = tid >> 5;
    const int lane = tid & 31;
    const int mt    = w >> 1;        // 0..1 : rows [mt*32, mt*32+32)
    const int nhalf = w & 1;
    const int r0    = lane >> 2;
    const int cpos  = lane & 3;
    const int hrot  = (r0 >> 1) & 3;

    uint32_t* sW1u = (uint32_t*)(smem + OFF_W1);
    uint32_t* sW2u = (uint32_t*)(smem + OFF_W2);
    uint32_t* sHu  = (uint32_t*)(smem + OFF_H);

    // ---- stage weights (tf32, permuted-n cols, permuted-k rows) ----
    {
        const float* p = gw1 + (size_t)m * RR * CC;
        for (int i = tid; i < RR * CC; i += NT) {
            int k = i >> 6, f = i & 63;
            sW1u[PERMN(f) * 36 + ((k & 3) * 8 + (k >> 2))] = f2tf(p[i]);
        }
        const float* q = gw2 + (size_t)m * CC * CC;
        for (int i = tid; i < CC * CC; i += NT) {
            int k = i >> 6, f = i & 63;
            sW2u[PERMN(f) * 80 + PC2(k)] = f2tf(q[i]);
        }
    }

    const int fbase = nhalf * 32 + cpos * 8;

    float b1r[8], b2r[8];
    {
        float4 t0 = *(const float4*)(gb1 + m * CC + fbase);
        float4 t1 = *(const float4*)(gb1 + m * CC + fbase + 4);
        b1r[0]=t0.x; b1r[1]=t0.y; b1r[2]=t0.z; b1r[3]=t0.w;
        b1r[4]=t1.x; b1r[5]=t1.y; b1r[6]=t1.z; b1r[7]=t1.w;
        float4 s0 = *(const float4*)(gb2 + m * CC + fbase);
        float4 s1 = *(const float4*)(gb2 + m * CC + fbase + 4);
        b2r[0]=s0.x; b2r[1]=s0.y; b2r[2]=s0.z; b2r[3]=s0.w;
        b2r[4]=s1.x; b2r[5]=s1.y; b2r[6]=s1.z; b2r[7]=s1.w;
    }

    __syncthreads();   // weights visible

    // ---- hoist W1 B-fragments to registers (loop-invariant) ----
    uint32_t w1b[8][4];
    #pragma unroll
    for (int nt = 0; nt < 4; nt++) {
        const int n = nhalf * 32 + nt * 8 + r0;
        #pragma unroll
        for (int kt = 0; kt < 2; kt++)
            *(uint4*)w1b[nt * 2 + kt] = *(const uint4*)&sW1u[n * 36 + cpos * 8 + kt * 4];
    }

    float acc[8][3];
    #pragma unroll
    for (int q = 0; q < 8; q++) { acc[q][0] = 0.f; acc[q][1] = 0.f; acc[q][2] = 0.f; }

    const int rbase = mt * 32 + r0;
    const uint32_t* rbA0 = g_rbf2 + ((size_t)(a * 2 + 0) * NN) * 16;
    const uint32_t* rbA1 = g_rbf2 + ((size_t)(a * 2 + 1) * NN) * 16;
    const float*    upA  = g_up + (size_t)a * NN * 4;

    for (int bt = 0; bt < NN; bt += BT) {
        // ---- GEMM1: H = relu(rbf @ W1 + b1); A coalesced from global (L2) ----
        float hc[2][4][4];
        #pragma unroll
        for (int s = 0; s < 2; s++)
            #pragma unroll
            for (int nt = 0; nt < 4; nt++)
                #pragma unroll
                for (int j = 0; j < 4; j++) hc[s][nt][j] = 0.f;

        #pragma unroll
        for (int kt = 0; kt < 2; kt++) {
            const uint32_t* rb = kt ? rbA1 : rbA0;
            uint4 A0[2], A1[2];
            #pragma unroll
            for (int s = 0; s < 2; s++) {
                const int R = bt + rbase + s * 16;
                A0[s] = *(const uint4*)&rb[(size_t)R * 16 + cpos * 4];
                A1[s] = *(const uint4*)&rb[(size_t)(R + 8) * 16 + cpos * 4];
            }
            #pragma unroll
            for (int nt = 0; nt < 4; nt++) {
                const uint32_t* B = w1b[nt * 2 + kt];
                #pragma unroll
                for (int s = 0; s < 2; s++) {
                    mma_tf32(hc[s][nt], A0[s].x, A1[s].x, A0[s].y, A1[s].y, B[0], B[1]);
                    mma_tf32(hc[s][nt], A0[s].z, A1[s].z, A0[s].w, A1[s].w, B[2], B[3]);
                }
            }
        }

        // pair barrier: our pair's GEMM2 reads of the previous tile's H are done
        asm volatile("bar.sync %0, %1;" :: "r"(1 + mt), "r"(64) : "memory");

        // epilogue: bias+relu+cvt -> sH (row-rotated slots)
        #pragma unroll
        for (int s = 0; s < 2; s++) {
            const int R = rbase + s * 16;
            #pragma unroll
            for (int nt = 0; nt < 4; nt++) {
                #pragma unroll
                for (int j = 0; j < 2; j++) {
                    const int c  = fbase + nt * 2 + j;
                    const int sl = ((((c & 3) + hrot) & 3) * 20) + (c >> 2);
                    sHu[R * 80 + sl]       = f2tf(fmaxf(hc[s][nt][j]     + b1r[nt*2+j], 0.f));
                    sHu[(R + 8) * 80 + sl] = f2tf(fmaxf(hc[s][nt][2 + j] + b1r[nt*2+j], 0.f));
                }
            }
        }
        // pair barrier: H writes visible to partner warp
        asm volatile("bar.sync %0, %1;" :: "r"(1 + mt), "r"(64) : "memory");

        // ---- GEMM2: rad = H @ W2 ----
        float rc[2][4][4];
        #pragma unroll
        for (int s = 0; s < 2; s++)
            #pragma unroll
            for (int nt = 0; nt < 4; nt++)
                #pragma unroll
                for (int j = 0; j < 4; j++) rc[s][nt][j] = 0.f;

        const int aoff = ((cpos + hrot) & 3) * 20;
        #pragma unroll
        for (int kt = 0; kt < 4; kt++) {
            uint4 A0[2], A1[2];
            #pragma unroll
            for (int s = 0; s < 2; s++) {
                const int R = rbase + s * 16;
                A0[s] = *(const uint4*)&sHu[R * 80 + aoff + kt * 4];
                A1[s] = *(const uint4*)&sHu[(R + 8) * 80 + aoff + kt * 4];
            }
            #pragma unroll
            for (int nt = 0; nt < 4; nt++) {
                const int n = nhalf * 32 + nt * 8 + r0;
                uint4 B = *(const uint4*)&sW2u[n * 80 + cpos * 20 + kt * 4];
                #pragma unroll
                for (int s = 0; s < 2; s++) {
                    mma_tf32(rc[s][nt], A0[s].x, A1[s].x, A0[s].y, A1[s].y, B.x, B.y);
                    mma_tf32(rc[s][nt], A0[s].z, A1[s].z, A0[s].w, A1[s].w, B.z, B.w);
                }
            }
        }

        // ---- fused CG contraction: coalesced fragment reads from global ----
        #pragma unroll
        for (int s = 0; s < 2; s++) {
            #pragma unroll
            for (int rs = 0; rs < 2; rs++) {
                const int row  = rbase + s * 16 + rs * 8;
                const int grow = bt + row;
                if (grow == a) continue;   // diagonal mask
                if (m <= 1) {
                    float4 xa = *(const float4*)&g_x0p[((size_t)(0 + nhalf) * NN + grow) * 16 + cpos * 4];
                    float4 xb = *(const float4*)&g_x0p[((size_t)(2 + nhalf) * NN + grow) * 16 + cpos * 4];
                    float xs[8] = {xa.x, xa.y, xa.z, xa.w, xb.x, xb.y, xb.z, xb.w};
                    if (m == 0) {
                        #pragma unroll
                        for (int q = 0; q < 8; q++) {
                            float rad = rc[s][q >> 1][rs * 2 + (q & 1)] + b2r[q];
                            acc[q][0] = fmaf(rad, xs[q], acc[q][0]);
                        }
                    } else {
                        float4 uv = *(const float4*)&upA[(size_t)grow * 4];
                        #pragma unroll
                        for (int q = 0; q < 8; q++) {
                            float rad = rc[s][q >> 1][rs * 2 + (q & 1)] + b2r[q];
                            float t = rad * xs[q];
                            acc[q][0] = fmaf(uv.x, t, acc[q][0]);
                            acc[q][1] = fmaf(uv.y, t, acc[q][1]);
                            acc[q][2] = fmaf(uv.z, t, acc[q][2]);
                        }
                    }
                } else {
                    float xr[24];
                    #pragma unroll
                    for (int t = 0; t < 6; t++)
                        *(float4*)&xr[t * 4] =
                            *(const float4*)&g_x1p[((size_t)(t * 2 + nhalf) * NN + grow) * 16 + cpos * 4];
                    float4 uv = make_float4(0.f, 0.f, 0.f, 0.f);
                    if (m >= 3) uv = *(const float4*)&upA[(size_t)grow * 4];
                    #pragma unroll
                    for (int q = 0; q < 8; q++) {
                        float rad = rc[s][q >> 1][rs * 2 + (q & 1)] + b2r[q];
                        float xx = xr[3*q], xy = xr[3*q+1], xz = xr[3*q+2];
                        if (m == 2) {
                            acc[q][0] = fmaf(rad, xx, acc[q][0]);
                            acc[q][1] = fmaf(rad, xy, acc[q][1]);
                            acc[q][2] = fmaf(rad, xz, acc[q][2]);
                        } else if (m == 3) {
                            float dot = uv.x * xx + uv.y * xy + uv.z * xz;
                            acc[q][0] = fmaf(rad, dot, acc[q][0]);
                        } else {
                            float cx = uv.y * xz - uv.z * xy;
                            float cy = uv.z * xx - uv.x * xz;
                            float cz = uv.x * xy - uv.y * xx;
                            acc[q][0] = fmaf(rad, cx, acc[q][0]);
                            acc[q][1] = fmaf(rad, cy, acc[q][1]);
                            acc[q][2] = fmaf(rad, cz, acc[q][2]);
                        }
                    }
                }
            }
        }
    }

    // ---- cross-thread reduction (16 contributors per output channel) ----
    __syncthreads();
    float* sPart = smem;   // weights dead; 128*24 = 3072 floats
    {
        const int base = tid * 24;
        #pragma unroll
        for (int q = 0; q < 8; q++) {
            sPart[base + q * 3 + 0] = acc[q][0];
            sPart[base + q * 3 + 1] = acc[q][1];
            sPart[base + q * 3 + 2] = acc[q][2];
        }
    }
    __syncthreads();

    const float nm = rsqrtf((float)(NN - 1));
    float* out1 = out + NN * 2 * CC;

    for (int idx = tid; idx < CC * 3; idx += NT) {
        const int f    = idx / 3;
        const int comp = idx - f * 3;
        const int nh = f >> 5;
        const int cp = (f >> 3) & 3;
        const int q  = f & 7;
        float s = 0.0f;
        #pragma unroll
        for (int mm = 0; mm < 2; mm++) {
            #pragma unroll
            for (int rg = 0; rg < 8; rg++) {
                int tc = (mm * 2 + nh) * 32 + rg * 4 + cp;
                s += sPart[tc * 24 + q * 3 + comp];
            }
        }
        s *= nm;

        if (m == 0)      { if (comp == 0) out[a * 128 + f] = s; }
        else if (m == 1) { out1[a * 576 + f * 3 + comp] = s; }
        else if (m == 2) { out1[a * 576 + (64 + f) * 3 + comp] = s; }
        else if (m == 3) { if (comp == 0) out[a * 128 + 64 + f] = s; }
        else             { out1[a * 576 + (128 + f) * 3 + comp] = s; }
    }
}

extern "C" void kernel_launch(void* const* d_in, const int* in_sizes, int n_in,
                              void* d_out, int out_size) {
    const float* x0  = (const float*)d_in[0];
    const float* x1  = (const float*)d_in[1];
    const float* rbf = (const float*)d_in[2];
    const float* u   = (const float*)d_in[3];
    // d_in[4] = r_ij : unused (switching_fn == None)
    const float* w1  = (const float*)d_in[5];
    const float* b1  = (const float*)d_in[6];
    const float* w2  = (const float*)d_in[7];
    const float* b2  = (const float*)d_in[8];
    float* out = (float*)d_out;

    // 1) repack rbf -> tf32 fragment-coalesced
    prep_rbf2_kernel<<<(NN * NN * 2) / 256, 256>>>(rbf);
    // 2) repack x0/x1/u
    prep_misc_kernel<<<(NN * NN + 16 * NN) / 256, 256>>>(x0, x1, u);

    // 3) main fused kernel
    cudaFuncSetAttribute(conv_tfn_tc6_kernel,
                         cudaFuncAttributeMaxDynamicSharedMemorySize, SMEM_BYTES);
    dim3 grid(NN, 5);
    conv_tfn_tc6_kernel<<<grid, NT, SMEM_BYTES>>>(w1, b1, w2, b2, out);
}

// round 12
// speedup vs baseline: 1.5049x; 1.5049x over previous
#include <cuda_runtime.h>
#include <cstdint>

#define NN 512
#define CC 64
#define RR 32
#define BT 64
#define NT 128

// mma n-column for physical channel f (each thread owns 8 contiguous f)
#define PERMN(f) (((f) & 32) + ((((f) & 7) >> 1) << 3) + ((((f) >> 3) & 3) << 1) + ((f) & 1))

// smem layout (uint32 units): fp16 pair-packed
#define OFF_W1   0        // [64 n][16]  | sPart overlay
#define OFF_W2   1024     // [64 n][36]  |
#define OFF_H    3328     // [64 b][36]
#define SMEM_U32 5632
#define SMEM_BYTES (SMEM_U32 * 4)   // 22528 B

// prep buffers
__device__ uint32_t g_rbfh[(size_t)NN * NN * 16];   // [a*512+b][16] fp16-pair frag layout
__device__ float    g_x0p[4 * NN * 16];             // [(t'*2+nh)*512+row][16]
__device__ float    g_x1p[12 * NN * 16];            // [(t*2+nh)*512+row][16]
__device__ float    g_up[(size_t)NN * NN * 4];      // [a*512+row][4] (xyz0)

extern __shared__ float smem[];

__device__ __forceinline__ uint32_t pack_h2(float lo, float hi) {
    uint32_t r;
    asm("cvt.rn.f16x2.f32 %0, %1, %2;" : "=r"(r) : "f"(hi), "f"(lo));
    return r;
}

__device__ __forceinline__ void mma_f16(float c[4], uint32_t a0, uint32_t a1,
                                        uint32_t a2, uint32_t a3,
                                        uint32_t b0, uint32_t b1) {
    asm volatile(
        "mma.sync.aligned.m16n8k16.row.col.f32.f16.f16.f32 "
        "{%0,%1,%2,%3}, {%4,%5,%6,%7}, {%8,%9}, {%0,%1,%2,%3};"
        : "+f"(c[0]), "+f"(c[1]), "+f"(c[2]), "+f"(c[3])
        : "r"(a0), "r"(a1), "r"(a2), "r"(a3), "r"(b0), "r"(b1));
}

// slot maps: k-pair q -> uint slot within a row (consumer reads are uint4/uint2-contiguous)
// k32 (W1/rbf): slot = (q&3)*4 + (q>>3)*2 + ((q>>2)&1)
// k64 (W2/H):   slot = (q&3)*8 + (q>>4)*4 + ((q>>3)&1)*2 + ((q>>2)&1)

// ---- prep 1: rbf fp32 -> fp16-pair fragment layout, one uint4 per thread ----
__global__ void prep_rbfh_kernel(const float* __restrict__ grbf) {
    int idx  = blockIdx.x * 256 + threadIdx.x;    // NN*NN*4
    int cpos = idx & 3;
    int rid  = idx >> 2;
    const float* src = grbf + (size_t)rid * RR;
    float2 p0 = *(const float2*)(src + 2 * cpos);
    float2 p1 = *(const float2*)(src + 2 * cpos + 8);
    float2 p2 = *(const float2*)(src + 2 * cpos + 16);
    float2 p3 = *(const float2*)(src + 2 * cpos + 24);
    uint4 v;
    v.x = pack_h2(p0.x, p0.y);   // kt0 h0
    v.y = pack_h2(p1.x, p1.y);   // kt0 h1
    v.z = pack_h2(p2.x, p2.y);   // kt1 h0
    v.w = pack_h2(p3.x, p3.y);   // kt1 h1
    *(uint4*)(g_rbfh + (size_t)rid * 16 + cpos * 4) = v;
}

// ---- prep 2: u padding + x0/x1 fragment repack (unchanged from R11) ----
__global__ void prep_misc_kernel(const float* __restrict__ gx0,
                                 const float* __restrict__ gx1,
                                 const float* __restrict__ gu) {
    int idx = blockIdx.x * 256 + threadIdx.x;
    if (idx < NN * NN) {
        const float* s = gu + (size_t)idx * 3;
        *(float4*)&g_up[(size_t)idx * 4] = make_float4(s[0], s[1], s[2], 0.f);
    } else {
        int j = idx - NN * NN;
        int slot = j >> 9, row = j & 511;
        if (slot < 4) {
            int tp = slot >> 1, nh = slot & 1;
            float* d = g_x0p + ((size_t)slot * NN + row) * 16;
            #pragma unroll
            for (int cpos = 0; cpos < 4; cpos++)
                #pragma unroll
                for (int e = 0; e < 4; e++)
                    d[cpos * 4 + e] = gx0[row * 64 + nh * 32 + cpos * 8 + tp * 4 + e];
        } else {
            int t = (slot - 4) >> 1, nh = (slot - 4) & 1;
            float* d = g_x1p + ((size_t)(slot - 4) * NN + row) * 16;
            #pragma unroll
            for (int cpos = 0; cpos < 4; cpos++)
                #pragma unroll
                for (int e = 0; e < 4; e++)
                    d[cpos * 4 + e] = gx1[row * 192 + nh * 96 + cpos * 24 + t * 4 + e];
        }
    }
}

__global__ __launch_bounds__(NT, 3)
void conv_tfn_h16_kernel(const float* __restrict__ gw1,
                         const float* __restrict__ gb1,
                         const float* __restrict__ gw2,
                         const float* __restrict__ gb2,
                         float* __restrict__ out)
{
    const int a    = blockIdx.x;
    const int m    = blockIdx.y;
    const int tid  = threadIdx.x;
    const int w    = tid >> 5;
    const int lane = tid & 31;
    const int mt    = w >> 1;
    const int nhalf = w & 1;
    const int r0    = lane >> 2;
    const int cpos  = lane & 3;

    uint32_t* sW1h = (uint32_t*)smem + OFF_W1;
    uint32_t* sW2h = (uint32_t*)smem + OFF_W2;
    uint32_t* sHh  = (uint32_t*)smem + OFF_H;

    // ---- stage weights as fp16 pairs (permuted-n cols, frag k-slots) ----
    {
        const float* p = gw1 + (size_t)m * RR * CC;
        for (int i = tid; i < CC * 16; i += NT) {       // q = k-pair 0..15
            int f = i & 63, q = i >> 6;
            int slot = (q & 3) * 4 + (q >> 3) * 2 + ((q >> 2) & 1);
            sW1h[PERMN(f) * 16 + slot] = pack_h2(p[(2 * q) * CC + f], p[(2 * q + 1) * CC + f]);
        }
        const float* qq = gw2 + (size_t)m * CC * CC;
        for (int i = tid; i < CC * 32; i += NT) {       // q = k-pair 0..31
            int f = i & 63, q = i >> 6;
            int slot = (q & 3) * 8 + (q >> 4) * 4 + ((q >> 3) & 1) * 2 + ((q >> 2) & 1);
            sW2h[PERMN(f) * 36 + slot] = pack_h2(qq[(2 * q) * CC + f], qq[(2 * q + 1) * CC + f]);
        }
    }

    const int fbase = nhalf * 32 + cpos * 8;

    float b1r[8], b2r[8];
    {
        float4 t0 = *(const float4*)(gb1 + m * CC + fbase);
        float4 t1 = *(const float4*)(gb1 + m * CC + fbase + 4);
        b1r[0]=t0.x; b1r[1]=t0.y; b1r[2]=t0.z; b1r[3]=t0.w;
        b1r[4]=t1.x; b1r[5]=t1.y; b1r[6]=t1.z; b1r[7]=t1.w;
        float4 s0 = *(const float4*)(gb2 + m * CC + fbase);
        float4 s1 = *(const float4*)(gb2 + m * CC + fbase + 4);
        b2r[0]=s0.x; b2r[1]=s0.y; b2r[2]=s0.z; b2r[3]=s0.w;
        b2r[4]=s1.x; b2r[5]=s1.y; b2r[6]=s1.z; b2r[7]=s1.w;
    }

    __syncthreads();   // weights visible

    // ---- hoist ALL B-fragments into registers ----
    uint32_t w1b[4][4];    // [nt][kt0h0,kt0h1,kt1h0,kt1h1]
    uint32_t w2b[4][8];    // [nt][kt*2+h]
    #pragma unroll
    for (int nt = 0; nt < 4; nt++) {
        const int n = nhalf * 32 + nt * 8 + r0;
        *(uint4*)w1b[nt]       = *(const uint4*)&sW1h[n * 16 + cpos * 4];
        *(uint4*)&w2b[nt][0]   = *(const uint4*)&sW2h[n * 36 + cpos * 8];
        *(uint4*)&w2b[nt][4]   = *(const uint4*)&sW2h[n * 36 + cpos * 8 + 4];
    }

    float acc[8][3];
    #pragma unroll
    for (int q = 0; q < 8; q++) { acc[q][0] = 0.f; acc[q][1] = 0.f; acc[q][2] = 0.f; }

    const int rbase = mt * 32 + r0;
    const uint32_t* rbA = g_rbfh + (size_t)a * NN * 16;
    const float*    upA = g_up + (size_t)a * NN * 4;

    for (int bt = 0; bt < NN; bt += BT) {
        // pair barrier: partner's GEMM2 H reads of previous tile are done
        asm volatile("bar.sync %0, %1;" :: "r"(1 + mt), "r"(64) : "memory");

        // ---- GEMM1 + epilogue, per 16-row subtile ----
        #pragma unroll
        for (int s = 0; s < 2; s++) {
            const int R = rbase + s * 16;
            uint4 va = *(const uint4*)&rbA[(size_t)(bt + R) * 16 + cpos * 4];
            uint4 vb = *(const uint4*)&rbA[(size_t)(bt + R + 8) * 16 + cpos * 4];
            float hc[4][4];
            #pragma unroll
            for (int nt = 0; nt < 4; nt++)
                #pragma unroll
                for (int j = 0; j < 4; j++) hc[nt][j] = 0.f;
            #pragma unroll
            for (int nt = 0; nt < 4; nt++) {
                mma_f16(hc[nt], va.x, vb.x, va.y, vb.y, w1b[nt][0], w1b[nt][1]);  // kt0
                mma_f16(hc[nt], va.z, vb.z, va.w, vb.w, w1b[nt][2], w1b[nt][3]);  // kt1
            }
            // epilogue: bias+relu, pack half2, conflict-free STS.32
            #pragma unroll
            for (int nt = 0; nt < 4; nt++) {
                const int sl = nt * 8 + nhalf * 4 + cpos;   // slot of pair p = fbase/2 + nt
                sHh[R * 36 + sl] =
                    pack_h2(fmaxf(hc[nt][0] + b1r[2*nt], 0.f),
                            fmaxf(hc[nt][1] + b1r[2*nt+1], 0.f));
                sHh[(R + 8) * 36 + sl] =
                    pack_h2(fmaxf(hc[nt][2] + b1r[2*nt], 0.f),
                            fmaxf(hc[nt][3] + b1r[2*nt+1], 0.f));
            }
        }
        // pair barrier: H visible to partner warp
        asm volatile("bar.sync %0, %1;" :: "r"(1 + mt), "r"(64) : "memory");

        // ---- GEMM2 + contraction, per 16-row subtile ----
        #pragma unroll
        for (int s = 0; s < 2; s++) {
            const int R = rbase + s * 16;
            uint4 x00 = *(const uint4*)&sHh[R * 36 + cpos * 8];          // row r0, kt0-1
            uint4 x01 = *(const uint4*)&sHh[R * 36 + cpos * 8 + 4];      // row r0, kt2-3
            uint4 x10 = *(const uint4*)&sHh[(R + 8) * 36 + cpos * 8];
            uint4 x11 = *(const uint4*)&sHh[(R + 8) * 36 + cpos * 8 + 4];
            float rc[4][4];
            #pragma unroll
            for (int nt = 0; nt < 4; nt++)
                #pragma unroll
                for (int j = 0; j < 4; j++) rc[nt][j] = 0.f;
            #pragma unroll
            for (int nt = 0; nt < 4; nt++) {
                mma_f16(rc[nt], x00.x, x10.x, x00.y, x10.y, w2b[nt][0], w2b[nt][1]);
                mma_f16(rc[nt], x00.z, x10.z, x00.w, x10.w, w2b[nt][2], w2b[nt][3]);
                mma_f16(rc[nt], x01.x, x11.x, x01.y, x11.y, w2b[nt][4], w2b[nt][5]);
                mma_f16(rc[nt], x01.z, x11.z, x01.w, x11.w, w2b[nt][6], w2b[nt][7]);
            }

            // fused CG contraction (fp32), coalesced x/u from prep buffers
            #pragma unroll
            for (int rs = 0; rs < 2; rs++) {
                const int grow = bt + R + rs * 8;
                if (grow == a) continue;   // diagonal mask
                if (m <= 1) {
                    float4 xa = *(const float4*)&g_x0p[((size_t)(0 + nhalf) * NN + grow) * 16 + cpos * 4];
                    float4 xb = *(const float4*)&g_x0p[((size_t)(2 + nhalf) * NN + grow) * 16 + cpos * 4];
                    float xs[8] = {xa.x, xa.y, xa.z, xa.w, xb.x, xb.y, xb.z, xb.w};
                    if (m == 0) {
                        #pragma unroll
                        for (int q = 0; q < 8; q++) {
                            float rad = rc[q >> 1][rs * 2 + (q & 1)] + b2r[q];
                            acc[q][0] = fmaf(rad, xs[q], acc[q][0]);
                        }
                    } else {
                        float4 uv = *(const float4*)&upA[(size_t)grow * 4];
                        #pragma unroll
                        for (int q = 0; q < 8; q++) {
                            float rad = rc[q >> 1][rs * 2 + (q & 1)] + b2r[q];
                            float t = rad * xs[q];
                            acc[q][0] = fmaf(uv.x, t, acc[q][0]);
                            acc[q][1] = fmaf(uv.y, t, acc[q][1]);
                            acc[q][2] = fmaf(uv.z, t, acc[q][2]);
                        }
                    }
                } else {
                    float xr[24];
                    #pragma unroll
                    for (int t = 0; t < 6; t++)
                        *(float4*)&xr[t * 4] =
                            *(const float4*)&g_x1p[((size_t)(t * 2 + nhalf) * NN + grow) * 16 + cpos * 4];
                    float4 uv = make_float4(0.f, 0.f, 0.f, 0.f);
                    if (m >= 3) uv = *(const float4*)&upA[(size_t)grow * 4];
                    #pragma unroll
                    for (int q = 0; q < 8; q++) {
                        float rad = rc[q >> 1][rs * 2 + (q & 1)] + b2r[q];
                        float xx = xr[3*q], xy = xr[3*q+1], xz = xr[3*q+2];
                        if (m == 2) {
                            acc[q][0] = fmaf(rad, xx, acc[q][0]);
                            acc[q][1] = fmaf(rad, xy, acc[q][1]);
                            acc[q][2] = fmaf(rad, xz, acc[q][2]);
                        } else if (m == 3) {
                            float dot = uv.x * xx + uv.y * xy + uv.z * xz;
                            acc[q][0] = fmaf(rad, dot, acc[q][0]);
                        } else {
                            float cx = uv.y * xz - uv.z * xy;
                            float cy = uv.z * xx - uv.x * xz;
                            float cz = uv.x * xy - uv.y * xx;
                            acc[q][0] = fmaf(rad, cx, acc[q][0]);
                            acc[q][1] = fmaf(rad, cy, acc[q][1]);
                            acc[q][2] = fmaf(rad, cz, acc[q][2]);
                        }
                    }
                }
            }
        }
    }

    // ---- cross-thread reduction (16 contributors per output channel) ----
    __syncthreads();
    float* sPart = smem;   // W regions dead (fragments in registers)
    {
        const int base = tid * 24;
        #pragma unroll
        for (int q = 0; q < 8; q++) {
            sPart[base + q * 3 + 0] = acc[q][0];
            sPart[base + q * 3 + 1] = acc[q][1];
            sPart[base + q * 3 + 2] = acc[q][2];
        }
    }
    __syncthreads();

    const float nm = rsqrtf((float)(NN - 1));
    float* out1 = out + NN * 2 * CC;

    for (int idx = tid; idx < CC * 3; idx += NT) {
        const int f    = idx / 3;
        const int comp = idx - f * 3;
        const int nh = f >> 5;
        const int cp = (f >> 3) & 3;
        const int q  = f & 7;
        float s = 0.0f;
        #pragma unroll
        for (int mm = 0; mm < 2; mm++) {
            #pragma unroll
            for (int rg = 0; rg < 8; rg++) {
                int tc = (mm * 2 + nh) * 32 + rg * 4 + cp;
                s += sPart[tc * 24 + q * 3 + comp];
            }
        }
        s *= nm;

        if (m == 0)      { if (comp == 0) out[a * 128 + f] = s; }
        else if (m == 1) { out1[a * 576 + f * 3 + comp] = s; }
        else if (m == 2) { out1[a * 576 + (64 + f) * 3 + comp] = s; }
        else if (m == 3) { if (comp == 0) out[a * 128 + 64 + f] = s; }
        else             { out1[a * 576 + (128 + f) * 3 + comp] = s; }
    }
}

extern "C" void kernel_launch(void* const* d_in, const int* in_sizes, int n_in,
                              void* d_out, int out_size) {
    const float* x0  = (const float*)d_in[0];
    const float* x1  = (const float*)d_in[1];
    const float* rbf = (const float*)d_in[2];
    const float* u   = (const float*)d_in[3];
    // d_in[4] = r_ij : unused (switching_fn == None)
    const float* w1  = (const float*)d_in[5];
    const float* b1  = (const float*)d_in[6];
    const float* w2  = (const float*)d_in[7];
    const float* b2  = (const float*)d_in[8];
    float* out = (float*)d_out;

    prep_rbfh_kernel<<<(NN * NN * 4) / 256, 256>>>(rbf);
    prep_misc_kernel<<<(NN * NN + 16 * NN) / 256, 256>>>(x0, x1, u);

    cudaFuncSetAttribute(conv_tfn_h16_kernel,
                         cudaFuncAttributeMaxDynamicSharedMemorySize, SMEM_BYTES);
    dim3 grid(NN, 5);
    conv_tfn_h16_kernel<<<grid, NT, SMEM_BYTES>>>(w1, b1, w2, b2, out);
}

// round 13
// speedup vs baseline: 1.5089x; 1.0027x over previous
#include <cuda_runtime.h>
#include <cuda_fp16.h>
#include <cstdint>

#define NN 512
#define CC 64
#define RR 32
#define BT 64
#define NT 128

// mma n-column for physical channel f (each thread owns 8 contiguous f)
#define PERMN(f) (((f) & 32) + ((((f) & 7) >> 1) << 3) + ((((f) >> 3) & 3) << 1) + ((f) & 1))

// smem layout (uint32 units): fp16 pair-packed
#define OFF_W1   0        // [64 n][16]          | sPart overlay
#define OFF_W2   1024     // [64 n][36]          |
#define OFF_H    3328     // 2 x [64 b][36] (double-buffered)
#define SMEM_U32 7936
#define SMEM_BYTES (SMEM_U32 * 4)   // 31744 B -> 3 CTAs/SM

// prep buffers
__device__ uint32_t g_rbfh[(size_t)NN * NN * 16];   // [a*512+b][16] fp16-pair frag layout
__device__ uint32_t g_x0h[2 * NN * 16];             // [(nh)*512+row][16] fp16 pairs
__device__ uint32_t g_x1h[6 * NN * 16];             // [(t*2+nh)*512+row][16] fp16 pairs
__device__ float    g_up[(size_t)NN * NN * 4];      // [a*512+row][4] (xyz0)

extern __shared__ float smem[];

__device__ __forceinline__ uint32_t pack_h2(float lo, float hi) {
    uint32_t r;
    asm("cvt.rn.f16x2.f32 %0, %1, %2;" : "=r"(r) : "f"(hi), "f"(lo));
    return r;
}

__device__ __forceinline__ float2 h2f(uint32_t h) {
    __half2 hh = *reinterpret_cast<__half2*>(&h);
    return __half22float2(hh);
}

__device__ __forceinline__ void mma_f16(float c[4], uint32_t a0, uint32_t a1,
                                        uint32_t a2, uint32_t a3,
                                        uint32_t b0, uint32_t b1) {
    asm volatile(
        "mma.sync.aligned.m16n8k16.row.col.f32.f16.f16.f32 "
        "{%0,%1,%2,%3}, {%4,%5,%6,%7}, {%8,%9}, {%0,%1,%2,%3};"
        : "+f"(c[0]), "+f"(c[1]), "+f"(c[2]), "+f"(c[3])
        : "r"(a0), "r"(a1), "r"(a2), "r"(a3), "r"(b0), "r"(b1));
}

// ---- prep 1: rbf fp32 -> fp16-pair fragment layout (one uint4 store/thread) ----
__global__ void prep_rbfh_kernel(const float* __restrict__ grbf) {
    int idx  = blockIdx.x * 256 + threadIdx.x;    // NN*NN*4
    int cpos = idx & 3;
    int rid  = idx >> 2;
    const float* src = grbf + (size_t)rid * RR;
    float2 p0 = *(const float2*)(src + 2 * cpos);
    float2 p1 = *(const float2*)(src + 2 * cpos + 8);
    float2 p2 = *(const float2*)(src + 2 * cpos + 16);
    float2 p3 = *(const float2*)(src + 2 * cpos + 24);
    uint4 v;
    v.x = pack_h2(p0.x, p0.y);
    v.y = pack_h2(p1.x, p1.y);
    v.z = pack_h2(p2.x, p2.y);
    v.w = pack_h2(p3.x, p3.y);
    *(uint4*)(g_rbfh + (size_t)rid * 16 + cpos * 4) = v;
}

// ---- prep 2: u pad + x0/x1 fp16 fragment repack ----
__global__ void prep_misc_kernel(const float* __restrict__ gx0,
                                 const float* __restrict__ gx1,
                                 const float* __restrict__ gu) {
    int idx = blockIdx.x * 256 + threadIdx.x;     // 262144 + 1024 + 3072 = 266240
    if (idx < NN * NN) {
        const float* s = gu + (size_t)idx * 3;
        *(float4*)&g_up[(size_t)idx * 4] = make_float4(s[0], s[1], s[2], 0.f);
    } else {
        int j = idx - NN * NN;
        if (j < 2 * NN) {                         // x0h
            int nh = j >> 9, row = j & 511;
            uint32_t* d = g_x0h + ((size_t)(nh * NN + row)) * 16;
            #pragma unroll
            for (int cpos = 0; cpos < 4; cpos++)
                #pragma unroll
                for (int e2 = 0; e2 < 4; e2++) {
                    const float* s = gx0 + row * 64 + nh * 32 + cpos * 8 + 2 * e2;
                    d[cpos * 4 + e2] = pack_h2(s[0], s[1]);
                }
        } else {                                  // x1h
            int jj = j - 2 * NN;
            int slot = jj >> 9, row = jj & 511;
            int t = slot >> 1, nh = slot & 1;
            uint32_t* d = g_x1h + ((size_t)(slot * NN + row)) * 16;
            #pragma unroll
            for (int cpos = 0; cpos < 4; cpos++)
                #pragma unroll
                for (int e2 = 0; e2 < 4; e2++) {
                    const float* s = gx1 + row * 192 + nh * 96 + cpos * 24 + t * 8 + 2 * e2;
                    d[cpos * 4 + e2] = pack_h2(s[0], s[1]);
                }
        }
    }
}

__global__ __launch_bounds__(NT, 3)
void conv_tfn_h17_kernel(const float* __restrict__ gw1,
                         const float* __restrict__ gb1,
                         const float* __restrict__ gw2,
                         const float* __restrict__ gb2,
                         float* __restrict__ out)
{
    const int a    = blockIdx.x;
    const int m    = blockIdx.y;
    const int tid  = threadIdx.x;
    const int w    = tid >> 5;
    const int lane = tid & 31;
    const int mt    = w >> 1;
    const int nhalf = w & 1;
    const int r0    = lane >> 2;
    const int cpos  = lane & 3;

    uint32_t* sW1h = (uint32_t*)smem + OFF_W1;
    uint32_t* sW2h = (uint32_t*)smem + OFF_W2;
    uint32_t* sHb  = (uint32_t*)smem + OFF_H;

    // ---- stage weights as fp16 pairs (permuted-n cols, frag k-slots) ----
    {
        const float* p = gw1 + (size_t)m * RR * CC;
        for (int i = tid; i < CC * 16; i += NT) {
            int f = i & 63, q = i >> 6;
            int slot = (q & 3) * 4 + (q >> 3) * 2 + ((q >> 2) & 1);
            sW1h[PERMN(f) * 16 + slot] = pack_h2(p[(2 * q) * CC + f], p[(2 * q + 1) * CC + f]);
        }
        const float* qq = gw2 + (size_t)m * CC * CC;
        for (int i = tid; i < CC * 32; i += NT) {
            int f = i & 63, q = i >> 6;
            int slot = (q & 3) * 8 + (q >> 4) * 4 + ((q >> 3) & 1) * 2 + ((q >> 2) & 1);
            sW2h[PERMN(f) * 36 + slot] = pack_h2(qq[(2 * q) * CC + f], qq[(2 * q + 1) * CC + f]);
        }
    }

    const int fbase = nhalf * 32 + cpos * 8;

    float b1r[8], b2r[8];
    {
        float4 t0 = *(const float4*)(gb1 + m * CC + fbase);
        float4 t1 = *(const float4*)(gb1 + m * CC + fbase + 4);
        b1r[0]=t0.x; b1r[1]=t0.y; b1r[2]=t0.z; b1r[3]=t0.w;
        b1r[4]=t1.x; b1r[5]=t1.y; b1r[6]=t1.z; b1r[7]=t1.w;
        float4 s0 = *(const float4*)(gb2 + m * CC + fbase);
        float4 s1 = *(const float4*)(gb2 + m * CC + fbase + 4);
        b2r[0]=s0.x; b2r[1]=s0.y; b2r[2]=s0.z; b2r[3]=s0.w;
        b2r[4]=s1.x; b2r[5]=s1.y; b2r[6]=s1.z; b2r[7]=s1.w;
    }

    __syncthreads();   // weights visible

    // ---- hoist ALL B-fragments into registers ----
    uint32_t w1b[4][4];
    uint32_t w2b[4][8];
    #pragma unroll
    for (int nt = 0; nt < 4; nt++) {
        const int n = nhalf * 32 + nt * 8 + r0;
        *(uint4*)w1b[nt]     = *(const uint4*)&sW1h[n * 16 + cpos * 4];
        *(uint4*)&w2b[nt][0] = *(const uint4*)&sW2h[n * 36 + cpos * 8];
        *(uint4*)&w2b[nt][4] = *(const uint4*)&sW2h[n * 36 + cpos * 8 + 4];
    }

    float acc[8][3];
    #pragma unroll
    for (int q = 0; q < 8; q++) { acc[q][0] = 0.f; acc[q][1] = 0.f; acc[q][2] = 0.f; }

    const int rbase = mt * 32 + r0;
    const uint32_t* rbA = g_rbfh + (size_t)a * NN * 16;
    const float*    upA = g_up + (size_t)a * NN * 4;

    int hb = 0;
    for (int bt = 0; bt < NN; bt += BT, hb ^= 1) {
        uint32_t* sHh = sHb + hb * 2304;

        // ---- GEMM1 + epilogue, per 16-row subtile (no barrier above: LDGs
        //      overlap the previous tile's contraction) ----
        #pragma unroll
        for (int s = 0; s < 2; s++) {
            const int R = rbase + s * 16;
            uint4 va = *(const uint4*)&rbA[(size_t)(bt + R) * 16 + cpos * 4];
            uint4 vb = *(const uint4*)&rbA[(size_t)(bt + R + 8) * 16 + cpos * 4];
            float hc[4][4];
            #pragma unroll
            for (int nt = 0; nt < 4; nt++)
                #pragma unroll
                for (int j = 0; j < 4; j++) hc[nt][j] = 0.f;
            #pragma unroll
            for (int nt = 0; nt < 4; nt++) {
                mma_f16(hc[nt], va.x, vb.x, va.y, vb.y, w1b[nt][0], w1b[nt][1]);
                mma_f16(hc[nt], va.z, vb.z, va.w, vb.w, w1b[nt][2], w1b[nt][3]);
            }
            #pragma unroll
            for (int nt = 0; nt < 4; nt++) {
                const int sl = nt * 8 + nhalf * 4 + cpos;
                sHh[R * 36 + sl] =
                    pack_h2(fmaxf(hc[nt][0] + b1r[2*nt], 0.f),
                            fmaxf(hc[nt][1] + b1r[2*nt+1], 0.f));
                sHh[(R + 8) * 36 + sl] =
                    pack_h2(fmaxf(hc[nt][2] + b1r[2*nt], 0.f),
                            fmaxf(hc[nt][3] + b1r[2*nt+1], 0.f));
            }
        }
        // single pair barrier per tile: H[hb] visible; partner's reads of the
        // other buffer finished strictly before its arrival here
        asm volatile("bar.sync %0, %1;" :: "r"(1 + mt), "r"(64) : "memory");

        // ---- GEMM2 + contraction, per 16-row subtile ----
        #pragma unroll
        for (int s = 0; s < 2; s++) {
            const int R = rbase + s * 16;
            uint4 x00 = *(const uint4*)&sHh[R * 36 + cpos * 8];
            uint4 x01 = *(const uint4*)&sHh[R * 36 + cpos * 8 + 4];
            uint4 x10 = *(const uint4*)&sHh[(R + 8) * 36 + cpos * 8];
            uint4 x11 = *(const uint4*)&sHh[(R + 8) * 36 + cpos * 8 + 4];
            float rc[4][4];
            #pragma unroll
            for (int nt = 0; nt < 4; nt++)
                #pragma unroll
                for (int j = 0; j < 4; j++) rc[nt][j] = 0.f;
            #pragma unroll
            for (int nt = 0; nt < 4; nt++) {
                mma_f16(rc[nt], x00.x, x10.x, x00.y, x10.y, w2b[nt][0], w2b[nt][1]);
                mma_f16(rc[nt], x00.z, x10.z, x00.w, x10.w, w2b[nt][2], w2b[nt][3]);
                mma_f16(rc[nt], x01.x, x11.x, x01.y, x11.y, w2b[nt][4], w2b[nt][5]);
                mma_f16(rc[nt], x01.z, x11.z, x01.w, x11.w, w2b[nt][6], w2b[nt][7]);
            }

            #pragma unroll
            for (int rs = 0; rs < 2; rs++) {
                const int grow = bt + R + rs * 8;
                if (grow == a) continue;   // diagonal mask
                if (m <= 1) {
                    uint4 xv = *(const uint4*)&g_x0h[((size_t)(nhalf * NN + grow)) * 16 + cpos * 4];
                    float2 p0 = h2f(xv.x), p1 = h2f(xv.y), p2 = h2f(xv.z), p3 = h2f(xv.w);
                    float xs[8] = {p0.x, p0.y, p1.x, p1.y, p2.x, p2.y, p3.x, p3.y};
                    if (m == 0) {
                        #pragma unroll
                        for (int q = 0; q < 8; q++) {
                            float rad = rc[q >> 1][rs * 2 + (q & 1)] + b2r[q];
                            acc[q][0] = fmaf(rad, xs[q], acc[q][0]);
                        }
                    } else {
                        float4 uv = *(const float4*)&upA[(size_t)grow * 4];
                        #pragma unroll
                        for (int q = 0; q < 8; q++) {
                            float rad = rc[q >> 1][rs * 2 + (q & 1)] + b2r[q];
                            float t = rad * xs[q];
                            acc[q][0] = fmaf(uv.x, t, acc[q][0]);
                            acc[q][1] = fmaf(uv.y, t, acc[q][1]);
                            acc[q][2] = fmaf(uv.z, t, acc[q][2]);
                        }
                    }
                } else {
                    float xr[24];
                    #pragma unroll
                    for (int t = 0; t < 3; t++) {
                        uint4 v = *(const uint4*)&g_x1h[((size_t)((t * 2 + nhalf) * NN + grow)) * 16 + cpos * 4];
                        float2 q0 = h2f(v.x), q1 = h2f(v.y), q2 = h2f(v.z), q3 = h2f(v.w);
                        xr[t*8+0] = q0.x; xr[t*8+1] = q0.y;
                        xr[t*8+2] = q1.x; xr[t*8+3] = q1.y;
                        xr[t*8+4] = q2.x; xr[t*8+5] = q2.y;
                        xr[t*8+6] = q3.x; xr[t*8+7] = q3.y;
                    }
                    float4 uv = make_float4(0.f, 0.f, 0.f, 0.f);
                    if (m >= 3) uv = *(const float4*)&upA[(size_t)grow * 4];
                    #pragma unroll
                    for (int q = 0; q < 8; q++) {
                        float rad = rc[q >> 1][rs * 2 + (q & 1)] + b2r[q];
                        float xx = xr[3*q], xy = xr[3*q+1], xz = xr[3*q+2];
                        if (m == 2) {
                            acc[q][0] = fmaf(rad, xx, acc[q][0]);
                            acc[q][1] = fmaf(rad, xy, acc[q][1]);
                            acc[q][2] = fmaf(rad, xz, acc[q][2]);
                        } else if (m == 3) {
                            float dot = uv.x * xx + uv.y * xy + uv.z * xz;
                            acc[q][0] = fmaf(rad, dot, acc[q][0]);
                        } else {
                            float cx = uv.y * xz - uv.z * xy;
                            float cy = uv.z * xx - uv.x * xz;
                            float cz = uv.x * xy - uv.y * xx;
                            acc[q][0] = fmaf(rad, cx, acc[q][0]);
                            acc[q][1] = fmaf(rad, cy, acc[q][1]);
                            acc[q][2] = fmaf(rad, cz, acc[q][2]);
                        }
                    }
                }
            }
        }
    }

    // ---- cross-thread reduction (16 contributors per output channel) ----
    __syncthreads();
    float* sPart = smem;   // W regions dead (fragments in registers); 3072 <= 3328
    {
        const int base = tid * 24;
        #pragma unroll
        for (int q = 0; q < 8; q++) {
            sPart[base + q * 3 + 0] = acc[q][0];
            sPart[base + q * 3 + 1] = acc[q][1];
            sPart[base + q * 3 + 2] = acc[q][2];
        }
    }
    __syncthreads();

    const float nm = rsqrtf((float)(NN - 1));
    float* out1 = out + NN * 2 * CC;

    for (int idx = tid; idx < CC * 3; idx += NT) {
        const int f    = idx / 3;
        const int comp = idx - f * 3;
        const int nh = f >> 5;
        const int cp = (f >> 3) & 3;
        const int q  = f & 7;
        float s = 0.0f;
        #pragma unroll
        for (int mm = 0; mm < 2; mm++) {
            #pragma unroll
            for (int rg = 0; rg < 8; rg++) {
                int tc = (mm * 2 + nh) * 32 + rg * 4 + cp;
                s += sPart[tc * 24 + q * 3 + comp];
            }
        }
        s *= nm;

        if (m == 0)      { if (comp == 0) out[a * 128 + f] = s; }
        else if (m == 1) { out1[a * 576 + f * 3 + comp] = s; }
        else if (m == 2) { out1[a * 576 + (64 + f) * 3 + comp] = s; }
        else if (m == 3) { if (comp == 0) out[a * 128 + 64 + f] = s; }
        else             { out1[a * 576 + (128 + f) * 3 + comp] = s; }
    }
}

extern "C" void kernel_launch(void* const* d_in, const int* in_sizes, int n_in,
                              void* d_out, int out_size) {
    const float* x0  = (const float*)d_in[0];
    const float* x1  = (const float*)d_in[1];
    const float* rbf = (const float*)d_in[2];
    const float* u   = (const float*)d_in[3];
    // d_in[4] = r_ij : unused (switching_fn == None)
    const float* w1  = (const float*)d_in[5];
    const float* b1  = (const float*)d_in[6];
    const float* w2  = (const float*)d_in[7];
    const float* b2  = (const float*)d_in[8];
    float* out = (float*)d_out;

    prep_rbfh_kernel<<<(NN * NN * 4) / 256, 256>>>(rbf);
    prep_misc_kernel<<<(NN * NN + 8 * NN) / 256, 256>>>(x0, x1, u);

    cudaFuncSetAttribute(conv_tfn_h17_kernel,
                         cudaFuncAttributeMaxDynamicSharedMemorySize, SMEM_BYTES);
    dim3 grid(NN, 5);
    conv_tfn_h17_kernel<<<grid, NT, SMEM_BYTES>>>(w1, b1, w2, b2, out);
}

// round 14
// speedup vs baseline: 1.5472x; 1.0254x over previous
#include <cuda_runtime.h>
#include <cuda_fp16.h>
#include <cstdint>

#define NN 512
#define CC 64
#define RR 32
#define BT 64
#define NT 128

// mma n-column for physical channel f (each thread owns 8 contiguous f)
#define PERMN(f) (((f) & 32) + ((((f) & 7) >> 1) << 3) + ((((f) >> 3) & 3) << 1) + ((f) & 1))

// smem layout (uint32 units): fp16 pair-packed
#define OFF_W1   0        // [64 n][16]          | sPart overlay
#define OFF_W2   1024     // [64 n][36]          |
#define OFF_H    3328     // 2 x [64 b][36] (double-buffered)
#define SMEM_U32 7936
#define SMEM_BYTES (SMEM_U32 * 4)   // 31744 B -> 4 CTAs/SM fits (127 KB)

// prep buffers
__device__ uint32_t g_rbfh[(size_t)NN * NN * 16];   // [a*512+b][16] fp16-pair frag layout
__device__ uint32_t g_x0h[2 * NN * 16];             // [(nh)*512+row][16] fp16 pairs
__device__ uint32_t g_x1h[6 * NN * 16];             // [(t*2+nh)*512+row][16] fp16 pairs
__device__ float    g_up[(size_t)NN * NN * 4];      // [a*512+row][4] (xyz0)

extern __shared__ float smem[];

__device__ __forceinline__ uint32_t pack_h2(float lo, float hi) {
    uint32_t r;
    asm("cvt.rn.f16x2.f32 %0, %1, %2;" : "=r"(r) : "f"(hi), "f"(lo));
    return r;
}

__device__ __forceinline__ float2 h2f(uint32_t h) {
    __half2 hh = *reinterpret_cast<__half2*>(&h);
    return __half22float2(hh);
}

__device__ __forceinline__ void mma_f16(float c[4], uint32_t a0, uint32_t a1,
                                        uint32_t a2, uint32_t a3,
                                        uint32_t b0, uint32_t b1) {
    asm volatile(
        "mma.sync.aligned.m16n8k16.row.col.f32.f16.f16.f32 "
        "{%0,%1,%2,%3}, {%4,%5,%6,%7}, {%8,%9}, {%0,%1,%2,%3};"
        : "+f"(c[0]), "+f"(c[1]), "+f"(c[2]), "+f"(c[3])
        : "r"(a0), "r"(a1), "r"(a2), "r"(a3), "r"(b0), "r"(b1));
}

// ---- prep 1: rbf fp32 -> fp16-pair fragment layout ----
__global__ void prep_rbfh_kernel(const float* __restrict__ grbf) {
    int idx  = blockIdx.x * 256 + threadIdx.x;    // NN*NN*4
    int cpos = idx & 3;
    int rid  = idx >> 2;
    const float* src = grbf + (size_t)rid * RR;
    float2 p0 = *(const float2*)(src + 2 * cpos);
    float2 p1 = *(const float2*)(src + 2 * cpos + 8);
    float2 p2 = *(const float2*)(src + 2 * cpos + 16);
    float2 p3 = *(const float2*)(src + 2 * cpos + 24);
    uint4 v;
    v.x = pack_h2(p0.x, p0.y);
    v.y = pack_h2(p1.x, p1.y);
    v.z = pack_h2(p2.x, p2.y);
    v.w = pack_h2(p3.x, p3.y);
    *(uint4*)(g_rbfh + (size_t)rid * 16 + cpos * 4) = v;
}

// ---- prep 2: u pad + x0/x1 fp16 fragment repack ----
__global__ void prep_misc_kernel(const float* __restrict__ gx0,
                                 const float* __restrict__ gx1,
                                 const float* __restrict__ gu) {
    int idx = blockIdx.x * 256 + threadIdx.x;
    if (idx < NN * NN) {
        const float* s = gu + (size_t)idx * 3;
        *(float4*)&g_up[(size_t)idx * 4] = make_float4(s[0], s[1], s[2], 0.f);
    } else {
        int j = idx - NN * NN;
        if (j < 2 * NN) {                         // x0h
            int nh = j >> 9, row = j & 511;
            uint32_t* d = g_x0h + ((size_t)(nh * NN + row)) * 16;
            #pragma unroll
            for (int cpos = 0; cpos < 4; cpos++)
                #pragma unroll
                for (int e2 = 0; e2 < 4; e2++) {
                    const float* s = gx0 + row * 64 + nh * 32 + cpos * 8 + 2 * e2;
                    d[cpos * 4 + e2] = pack_h2(s[0], s[1]);
                }
        } else {                                  // x1h
            int jj = j - 2 * NN;
            int slot = jj >> 9, row = jj & 511;
            int t = slot >> 1, nh = slot & 1;
            uint32_t* d = g_x1h + ((size_t)(slot * NN + row)) * 16;
            #pragma unroll
            for (int cpos = 0; cpos < 4; cpos++)
                #pragma unroll
                for (int e2 = 0; e2 < 4; e2++) {
                    const float* s = gx1 + row * 192 + nh * 96 + cpos * 24 + t * 8 + 2 * e2;
                    d[cpos * 4 + e2] = pack_h2(s[0], s[1]);
                }
        }
    }
}

__global__ __launch_bounds__(NT, 4)
void conv_tfn_h18_kernel(const float* __restrict__ gw1,
                         const float* __restrict__ gb1,
                         const float* __restrict__ gw2,
                         const float* __restrict__ gb2,
                         float* __restrict__ out)
{
    const int a    = blockIdx.x;
    const int m    = blockIdx.y;
    const int tid  = threadIdx.x;
    const int w    = tid >> 5;
    const int lane = tid & 31;
    const int mt    = w >> 1;
    const int nhalf = w & 1;
    const int r0    = lane >> 2;
    const int cpos  = lane & 3;

    uint32_t* sW1h = (uint32_t*)smem + OFF_W1;
    uint32_t* sW2h = (uint32_t*)smem + OFF_W2;
    uint32_t* sHb  = (uint32_t*)smem + OFF_H;

    // ---- stage weights as fp16 pairs (permuted-n cols, frag k-slots) ----
    {
        const float* p = gw1 + (size_t)m * RR * CC;
        for (int i = tid; i < CC * 16; i += NT) {
            int f = i & 63, q = i >> 6;
            int slot = (q & 3) * 4 + (q >> 3) * 2 + ((q >> 2) & 1);
            sW1h[PERMN(f) * 16 + slot] = pack_h2(p[(2 * q) * CC + f], p[(2 * q + 1) * CC + f]);
        }
        const float* qq = gw2 + (size_t)m * CC * CC;
        for (int i = tid; i < CC * 32; i += NT) {
            int f = i & 63, q = i >> 6;
            int slot = (q & 3) * 8 + (q >> 4) * 4 + ((q >> 3) & 1) * 2 + ((q >> 2) & 1);
            sW2h[PERMN(f) * 36 + slot] = pack_h2(qq[(2 * q) * CC + f], qq[(2 * q + 1) * CC + f]);
        }
    }

    const int fbase = nhalf * 32 + cpos * 8;

    float b1r[8], b2r[8];
    {
        float4 t0 = *(const float4*)(gb1 + m * CC + fbase);
        float4 t1 = *(const float4*)(gb1 + m * CC + fbase + 4);
        b1r[0]=t0.x; b1r[1]=t0.y; b1r[2]=t0.z; b1r[3]=t0.w;
        b1r[4]=t1.x; b1r[5]=t1.y; b1r[6]=t1.z; b1r[7]=t1.w;
        float4 s0 = *(const float4*)(gb2 + m * CC + fbase);
        float4 s1 = *(const float4*)(gb2 + m * CC + fbase + 4);
        b2r[0]=s0.x; b2r[1]=s0.y; b2r[2]=s0.z; b2r[3]=s0.w;
        b2r[4]=s1.x; b2r[5]=s1.y; b2r[6]=s1.z; b2r[7]=s1.w;
    }

    __syncthreads();   // weights visible

    // ---- hoist only W1 B-fragments (16 regs); W2 stays in smem ----
    uint32_t w1b[4][4];
    #pragma unroll
    for (int nt = 0; nt < 4; nt++) {
        const int n = nhalf * 32 + nt * 8 + r0;
        *(uint4*)w1b[nt] = *(const uint4*)&sW1h[n * 16 + cpos * 4];
    }

    float acc[8][3];
    #pragma unroll
    for (int q = 0; q < 8; q++) { acc[q][0] = 0.f; acc[q][1] = 0.f; acc[q][2] = 0.f; }

    const int rbase = mt * 32 + r0;
    const int nrow  = nhalf * 32 + r0;    // W2 B row base (n = nrow + nt*8)
    const uint32_t* rbA = g_rbfh + (size_t)a * NN * 16;
    const float*    upA = g_up + (size_t)a * NN * 4;

    int hb = 0;
    for (int bt = 0; bt < NN; bt += BT, hb ^= 1) {
        uint32_t* sHh = sHb + hb * 2304;

        // ---- GEMM1 + epilogue, per 16-row subtile ----
        #pragma unroll
        for (int s = 0; s < 2; s++) {
            const int R = rbase + s * 16;
            uint4 va = *(const uint4*)&rbA[(size_t)(bt + R) * 16 + cpos * 4];
            uint4 vb = *(const uint4*)&rbA[(size_t)(bt + R + 8) * 16 + cpos * 4];
            float hc[4][4];
            #pragma unroll
            for (int nt = 0; nt < 4; nt++)
                #pragma unroll
                for (int j = 0; j < 4; j++) hc[nt][j] = 0.f;
            #pragma unroll
            for (int nt = 0; nt < 4; nt++) {
                mma_f16(hc[nt], va.x, vb.x, va.y, vb.y, w1b[nt][0], w1b[nt][1]);
                mma_f16(hc[nt], va.z, vb.z, va.w, vb.w, w1b[nt][2], w1b[nt][3]);
            }
            #pragma unroll
            for (int nt = 0; nt < 4; nt++) {
                const int sl = nt * 8 + nhalf * 4 + cpos;
                sHh[R * 36 + sl] =
                    pack_h2(fmaxf(hc[nt][0] + b1r[2*nt], 0.f),
                            fmaxf(hc[nt][1] + b1r[2*nt+1], 0.f));
                sHh[(R + 8) * 36 + sl] =
                    pack_h2(fmaxf(hc[nt][2] + b1r[2*nt], 0.f),
                            fmaxf(hc[nt][3] + b1r[2*nt+1], 0.f));
            }
        }
        // single pair barrier per tile (double-buffered H)
        asm volatile("bar.sync %0, %1;" :: "r"(1 + mt), "r"(64) : "memory");

        // ---- GEMM2 + contraction, per 16-row subtile ----
        #pragma unroll
        for (int s = 0; s < 2; s++) {
            const int R = rbase + s * 16;
            uint4 x00 = *(const uint4*)&sHh[R * 36 + cpos * 8];
            uint4 x01 = *(const uint4*)&sHh[R * 36 + cpos * 8 + 4];
            uint4 x10 = *(const uint4*)&sHh[(R + 8) * 36 + cpos * 8];
            uint4 x11 = *(const uint4*)&sHh[(R + 8) * 36 + cpos * 8 + 4];
            float rc[4][4];
            #pragma unroll
            for (int nt = 0; nt < 4; nt++)
                #pragma unroll
                for (int j = 0; j < 4; j++) rc[nt][j] = 0.f;
            #pragma unroll
            for (int nt = 0; nt < 4; nt++) {
                const int n = nrow + nt * 8;
                uint4 B0 = *(const uint4*)&sW2h[n * 36 + cpos * 8];
                uint4 B1 = *(const uint4*)&sW2h[n * 36 + cpos * 8 + 4];
                mma_f16(rc[nt], x00.x, x10.x, x00.y, x10.y, B0.x, B0.y);
                mma_f16(rc[nt], x00.z, x10.z, x00.w, x10.w, B0.z, B0.w);
                mma_f16(rc[nt], x01.x, x11.x, x01.y, x11.y, B1.x, B1.y);
                mma_f16(rc[nt], x01.z, x11.z, x01.w, x11.w, B1.z, B1.w);
            }

            #pragma unroll
            for (int rs = 0; rs < 2; rs++) {
                const int grow = bt + R + rs * 8;
                if (grow == a) continue;   // diagonal mask
                if (m <= 1) {
                    uint4 xv = *(const uint4*)&g_x0h[((size_t)(nhalf * NN + grow)) * 16 + cpos * 4];
                    float2 p0 = h2f(xv.x), p1 = h2f(xv.y), p2 = h2f(xv.z), p3 = h2f(xv.w);
                    float xs[8] = {p0.x, p0.y, p1.x, p1.y, p2.x, p2.y, p3.x, p3.y};
                    if (m == 0) {
                        #pragma unroll
                        for (int q = 0; q < 8; q++) {
                            float rad = rc[q >> 1][rs * 2 + (q & 1)] + b2r[q];
                            acc[q][0] = fmaf(rad, xs[q], acc[q][0]);
                        }
                    } else {
                        float4 uv = *(const float4*)&upA[(size_t)grow * 4];
                        #pragma unroll
                        for (int q = 0; q < 8; q++) {
                            float rad = rc[q >> 1][rs * 2 + (q & 1)] + b2r[q];
                            float t = rad * xs[q];
                            acc[q][0] = fmaf(uv.x, t, acc[q][0]);
                            acc[q][1] = fmaf(uv.y, t, acc[q][1]);
                            acc[q][2] = fmaf(uv.z, t, acc[q][2]);
                        }
                    }
                } else {
                    float xr[24];
                    #pragma unroll
                    for (int t = 0; t < 3; t++) {
                        uint4 v = *(const uint4*)&g_x1h[((size_t)((t * 2 + nhalf) * NN + grow)) * 16 + cpos * 4];
                        float2 q0 = h2f(v.x), q1 = h2f(v.y), q2 = h2f(v.z), q3 = h2f(v.w);
                        xr[t*8+0] = q0.x; xr[t*8+1] = q0.y;
                        xr[t*8+2] = q1.x; xr[t*8+3] = q1.y;
                        xr[t*8+4] = q2.x; xr[t*8+5] = q2.y;
                        xr[t*8+6] = q3.x; xr[t*8+7] = q3.y;
                    }
                    float4 uv = make_float4(0.f, 0.f, 0.f, 0.f);
                    if (m >= 3) uv = *(const float4*)&upA[(size_t)grow * 4];
                    #pragma unroll
                    for (int q = 0; q < 8; q++) {
                        float rad = rc[q >> 1][rs * 2 + (q & 1)] + b2r[q];
                        float xx = xr[3*q], xy = xr[3*q+1], xz = xr[3*q+2];
                        if (m == 2) {
                            acc[q][0] = fmaf(rad, xx, acc[q][0]);
                            acc[q][1] = fmaf(rad, xy, acc[q][1]);
                            acc[q][2] = fmaf(rad, xz, acc[q][2]);
                        } else if (m == 3) {
                            float dot = uv.x * xx + uv.y * xy + uv.z * xz;
                            acc[q][0] = fmaf(rad, dot, acc[q][0]);
                        } else {
                            float cx = uv.y * xz - uv.z * xy;
                            float cy = uv.z * xx - uv.x * xz;
                            float cz = uv.x * xy - uv.y * xx;
                            acc[q][0] = fmaf(rad, cx, acc[q][0]);
                            acc[q][1] = fmaf(rad, cy, acc[q][1]);
                            acc[q][2] = fmaf(rad, cz, acc[q][2]);
                        }
                    }
                }
            }
        }
    }

    // ---- cross-thread reduction (16 contributors per output channel) ----
    __syncthreads();
    float* sPart = smem;   // W1/W2 regions dead; 3072 <= 3328 floats
    {
        const int base = tid * 24;
        #pragma unroll
        for (int q = 0; q < 8; q++) {
            sPart[base + q * 3 + 0] = acc[q][0];
            sPart[base + q * 3 + 1] = acc[q][1];
            sPart[base + q * 3 + 2] = acc[q][2];
        }
    }
    __syncthreads();

    const float nm = rsqrtf((float)(NN - 1));
    float* out1 = out + NN * 2 * CC;

    for (int idx = tid; idx < CC * 3; idx += NT) {
        const int f    = idx / 3;
        const int comp = idx - f * 3;
        const int nh = f >> 5;
        const int cp = (f >> 3) & 3;
        const int q  = f & 7;
        float s = 0.0f;
        #pragma unroll
        for (int mm = 0; mm < 2; mm++) {
            #pragma unroll
            for (int rg = 0; rg < 8; rg++) {
                int tc = (mm * 2 + nh) * 32 + rg * 4 + cp;
                s += sPart[tc * 24 + q * 3 + comp];
            }
        }
        s *= nm;

        if (m == 0)      { if (comp == 0) out[a * 128 + f] = s; }
        else if (m == 1) { out1[a * 576 + f * 3 + comp] = s; }
        else if (m == 2) { out1[a * 576 + (64 + f) * 3 + comp] = s; }
        else if (m == 3) { if (comp == 0) out[a * 128 + 64 + f] = s; }
        else             { out1[a * 576 + (128 + f) * 3 + comp] = s; }
    }
}

extern "C" void kernel_launch(void* const* d_in, const int* in_sizes, int n_in,
                              void* d_out, int out_size) {
    const float* x0  = (const float*)d_in[0];
    const float* x1  = (const float*)d_in[1];
    const float* rbf = (const float*)d_in[2];
    const float* u   = (const float*)d_in[3];
    // d_in[4] = r_ij : unused (switching_fn == None)
    const float* w1  = (const float*)d_in[5];
    const float* b1  = (const float*)d_in[6];
    const float* w2  = (const float*)d_in[7];
    const float* b2  = (const float*)d_in[8];
    float* out = (float*)d_out;

    prep_rbfh_kernel<<<(NN * NN * 4) / 256, 256>>>(rbf);
    prep_misc_kernel<<<(NN * NN + 8 * NN) / 256, 256>>>(x0, x1, u);

    cudaFuncSetAttribute(conv_tfn_h18_kernel,
                         cudaFuncAttributeMaxDynamicSharedMemorySize, SMEM_BYTES);
    dim3 grid(NN, 5);
    conv_tfn_h18_kernel<<<grid, NT, SMEM_BYTES>>>(w1, b1, w2, b2, out);
}

// round 15
// speedup vs baseline: 1.8819x; 1.2163x over previous
#include <cuda_runtime.h>
#include <cuda_fp16.h>
#include <cstdint>

#define NN 512
#define CC 64
#define RR 32
#define BT 64
#define NT 128

typedef unsigned long long ull;

// mma n-column for physical channel f (each thread owns 8 contiguous f)
#define PERMN(f) (((f) & 32) + ((((f) & 7) >> 1) << 3) + ((((f) >> 3) & 3) << 1) + ((f) & 1))

// smem layout (uint32 units): fp16 pair-packed
#define OFF_W1   0        // [64 n][16]          | sPart overlay
#define OFF_W2   1024     // [64 n][36]          |
#define OFF_H    3328     // 2 x [64 b][36] (double-buffered)
#define SMEM_U32 7936
#define SMEM_BYTES (SMEM_U32 * 4)   // 31744 B

// prep buffers
__device__ uint32_t g_rbfh[(size_t)NN * NN * 16];    // fp16-pair GEMM1 A fragments
__device__ float    g_x0f[4 * NN * 16];              // [slot=ph*2+nh][row][16] fp32 pairs
__device__ float    g_x1f[12 * NN * 16];             // [slot=c*4+ph*2+nh][row][16] fp32 pairs
__device__ float    g_upx[(size_t)NN * NN * 12];     // [a*512+row][12]: u0u0u1u1 u2u2 -u0-u0 -u1-u1 -u2-u2

extern __shared__ float smem[];

__device__ __forceinline__ uint32_t pack_h2(float lo, float hi) {
    uint32_t r;
    asm("cvt.rn.f16x2.f32 %0, %1, %2;" : "=r"(r) : "f"(hi), "f"(lo));
    return r;
}

__device__ __forceinline__ ull pk2(float lo, float hi) {
    ull d;
    asm("mov.b64 %0, {%1, %2};" : "=l"(d) : "f"(lo), "f"(hi));
    return d;
}
__device__ __forceinline__ void upk2(float& lo, float& hi, ull v) {
    asm("mov.b64 {%0, %1}, %2;" : "=f"(lo), "=f"(hi) : "l"(v));
}
__device__ __forceinline__ ull fma2(ull a, ull b, ull c) {
    ull d;
    asm("fma.rn.f32x2 %0, %1, %2, %3;" : "=l"(d) : "l"(a), "l"(b), "l"(c));
    return d;
}
__device__ __forceinline__ ull mul2(ull a, ull b) {
    ull d;
    asm("mul.rn.f32x2 %0, %1, %2;" : "=l"(d) : "l"(a), "l"(b));
    return d;
}
__device__ __forceinline__ ull add2(ull a, ull b) {
    ull d;
    asm("add.rn.f32x2 %0, %1, %2;" : "=l"(d) : "l"(a), "l"(b));
    return d;
}

__device__ __forceinline__ void mma_f16(float c[4], uint32_t a0, uint32_t a1,
                                        uint32_t a2, uint32_t a3,
                                        uint32_t b0, uint32_t b1) {
    asm volatile(
        "mma.sync.aligned.m16n8k16.row.col.f32.f16.f16.f32 "
        "{%0,%1,%2,%3}, {%4,%5,%6,%7}, {%8,%9}, {%0,%1,%2,%3};"
        : "+f"(c[0]), "+f"(c[1]), "+f"(c[2]), "+f"(c[3])
        : "r"(a0), "r"(a1), "r"(a2), "r"(a3), "r"(b0), "r"(b1));
}

// ---- prep 1: rbf fp32 -> fp16-pair fragment layout ----
__global__ void prep_rbfh_kernel(const float* __restrict__ grbf) {
    int idx  = blockIdx.x * 256 + threadIdx.x;    // NN*NN*4
    int cpos = idx & 3;
    int rid  = idx >> 2;
    const float* src = grbf + (size_t)rid * RR;
    float2 p0 = *(const float2*)(src + 2 * cpos);
    float2 p1 = *(const float2*)(src + 2 * cpos + 8);
    float2 p2 = *(const float2*)(src + 2 * cpos + 16);
    float2 p3 = *(const float2*)(src + 2 * cpos + 24);
    uint4 v;
    v.x = pack_h2(p0.x, p0.y);
    v.y = pack_h2(p1.x, p1.y);
    v.z = pack_h2(p2.x, p2.y);
    v.w = pack_h2(p3.x, p3.y);
    *(uint4*)(g_rbfh + (size_t)rid * 16 + cpos * 4) = v;
}

// ---- prep 2: u broadcast/neg pairs + x0/x1 fp32 planar-pair repack ----
__global__ void prep_misc_kernel(const float* __restrict__ gx0,
                                 const float* __restrict__ gx1,
                                 const float* __restrict__ gu) {
    int idx = blockIdx.x * 256 + threadIdx.x;     // 786432 + 8192 + 24576 = 819200
    if (idx < NN * NN * 3) {
        int part = idx % 3;
        int rid  = idx / 3;
        const float* s = gu + (size_t)rid * 3;
        float u0 = s[0], u1 = s[1], u2 = s[2];
        float4 v;
        if (part == 0)      v = make_float4(u0, u0, u1, u1);
        else if (part == 1) v = make_float4(u2, u2, -u0, -u0);
        else                v = make_float4(-u1, -u1, -u2, -u2);
        *(float4*)&g_upx[(size_t)rid * 12 + part * 4] = v;
    } else {
        int j = idx - NN * NN * 3;
        if (j < 4 * NN * 4) {                     // x0f
            int cpos = j & 3, row = (j >> 2) & 511, slot = j >> 11;   // slot=ph*2+nh
            int ph = slot >> 1, nh = slot & 1;
            const float* s = gx0 + row * 64 + nh * 32 + cpos * 8 + ph * 4;
            *(float4*)&g_x0f[((size_t)slot * NN + row) * 16 + cpos * 4] =
                make_float4(s[0], s[1], s[2], s[3]);
        } else {                                  // x1f
            int j2 = j - 4 * NN * 4;
            int cpos = j2 & 3, row = (j2 >> 2) & 511, slot = j2 >> 11; // slot=c*4+ph*2+nh
            int nh = slot & 1, ph = (slot >> 1) & 1, c = slot >> 2;
            int fb = nh * 32 + cpos * 8 + ph * 4;
            const float* s = gx1 + row * 192;
            *(float4*)&g_x1f[((size_t)slot * NN + row) * 16 + cpos * 4] =
                make_float4(s[(fb + 0) * 3 + c], s[(fb + 1) * 3 + c],
                            s[(fb + 2) * 3 + c], s[(fb + 3) * 3 + c]);
        }
    }
}

__global__ __launch_bounds__(NT, 4)
void conv_tfn_h19_kernel(const float* __restrict__ gw1,
                         const float* __restrict__ gb1,
                         const float* __restrict__ gw2,
                         const float* __restrict__ gb2,
                         float* __restrict__ out)
{
    const int a    = blockIdx.x;
    const int m    = blockIdx.y;
    const int tid  = threadIdx.x;
    const int w    = tid >> 5;
    const int lane = tid & 31;
    const int mt    = w >> 1;
    const int nhalf = w & 1;
    const int r0    = lane >> 2;
    const int cpos  = lane & 3;

    uint32_t* sW1h = (uint32_t*)smem + OFF_W1;
    uint32_t* sW2h = (uint32_t*)smem + OFF_W2;
    uint32_t* sHb  = (uint32_t*)smem + OFF_H;

    // ---- stage weights as fp16 pairs (permuted-n cols, frag k-slots) ----
    {
        const float* p = gw1 + (size_t)m * RR * CC;
        for (int i = tid; i < CC * 16; i += NT) {
            int f = i & 63, q = i >> 6;
            int slot = (q & 3) * 4 + (q >> 3) * 2 + ((q >> 2) & 1);
            sW1h[PERMN(f) * 16 + slot] = pack_h2(p[(2 * q) * CC + f], p[(2 * q + 1) * CC + f]);
        }
        const float* qq = gw2 + (size_t)m * CC * CC;
        for (int i = tid; i < CC * 32; i += NT) {
            int f = i & 63, q = i >> 6;
            int slot = (q & 3) * 8 + (q >> 4) * 4 + ((q >> 3) & 1) * 2 + ((q >> 2) & 1);
            sW2h[PERMN(f) * 36 + slot] = pack_h2(qq[(2 * q) * CC + f], qq[(2 * q + 1) * CC + f]);
        }
    }

    const int fbase = nhalf * 32 + cpos * 8;

    float b1r[8];
    ull b2p[4];
    {
        float4 t0 = *(const float4*)(gb1 + m * CC + fbase);
        float4 t1 = *(const float4*)(gb1 + m * CC + fbase + 4);
        b1r[0]=t0.x; b1r[1]=t0.y; b1r[2]=t0.z; b1r[3]=t0.w;
        b1r[4]=t1.x; b1r[5]=t1.y; b1r[6]=t1.z; b1r[7]=t1.w;
        float4 s0 = *(const float4*)(gb2 + m * CC + fbase);
        float4 s1 = *(const float4*)(gb2 + m * CC + fbase + 4);
        b2p[0] = pk2(s0.x, s0.y);
        b2p[1] = pk2(s0.z, s0.w);
        b2p[2] = pk2(s1.x, s1.y);
        b2p[3] = pk2(s1.z, s1.w);
    }

    __syncthreads();   // weights visible

    // ---- hoist W1 B-fragments (16 regs); W2 stays in smem ----
    uint32_t w1b[4][4];
    #pragma unroll
    for (int nt = 0; nt < 4; nt++) {
        const int n = nhalf * 32 + nt * 8 + r0;
        *(uint4*)w1b[nt] = *(const uint4*)&sW1h[n * 16 + cpos * 4];
    }

    ull acc2[4][3];   // [q-pair][component], f32x2 accumulators
    #pragma unroll
    for (int i = 0; i < 4; i++) { acc2[i][0] = 0; acc2[i][1] = 0; acc2[i][2] = 0; }

    const int rbase = mt * 32 + r0;
    const int nrow  = nhalf * 32 + r0;
    const uint32_t* rbA = g_rbfh + (size_t)a * NN * 16;
    const float*    upA = g_upx + (size_t)a * NN * 12;

    int hb = 0;
    for (int bt = 0; bt < NN; bt += BT, hb ^= 1) {
        uint32_t* sHh = sHb + hb * 2304;

        // ---- GEMM1 + epilogue, per 16-row subtile ----
        #pragma unroll
        for (int s = 0; s < 2; s++) {
            const int R = rbase + s * 16;
            uint4 va = *(const uint4*)&rbA[(size_t)(bt + R) * 16 + cpos * 4];
            uint4 vb = *(const uint4*)&rbA[(size_t)(bt + R + 8) * 16 + cpos * 4];
            float hc[4][4];
            #pragma unroll
            for (int nt = 0; nt < 4; nt++)
                #pragma unroll
                for (int j = 0; j < 4; j++) hc[nt][j] = 0.f;
            #pragma unroll
            for (int nt = 0; nt < 4; nt++) {
                mma_f16(hc[nt], va.x, vb.x, va.y, vb.y, w1b[nt][0], w1b[nt][1]);
                mma_f16(hc[nt], va.z, vb.z, va.w, vb.w, w1b[nt][2], w1b[nt][3]);
            }
            #pragma unroll
            for (int nt = 0; nt < 4; nt++) {
                const int sl = nt * 8 + nhalf * 4 + cpos;
                sHh[R * 36 + sl] =
                    pack_h2(fmaxf(hc[nt][0] + b1r[2*nt], 0.f),
                            fmaxf(hc[nt][1] + b1r[2*nt+1], 0.f));
                sHh[(R + 8) * 36 + sl] =
                    pack_h2(fmaxf(hc[nt][2] + b1r[2*nt], 0.f),
                            fmaxf(hc[nt][3] + b1r[2*nt+1], 0.f));
            }
        }
        // single pair barrier per tile (double-buffered H)
        asm volatile("bar.sync %0, %1;" :: "r"(1 + mt), "r"(64) : "memory");

        // ---- GEMM2 + contraction, per 16-row subtile ----
        #pragma unroll
        for (int s = 0; s < 2; s++) {
            const int R = rbase + s * 16;
            uint4 x00 = *(const uint4*)&sHh[R * 36 + cpos * 8];
            uint4 x01 = *(const uint4*)&sHh[R * 36 + cpos * 8 + 4];
            uint4 x10 = *(const uint4*)&sHh[(R + 8) * 36 + cpos * 8];
            uint4 x11 = *(const uint4*)&sHh[(R + 8) * 36 + cpos * 8 + 4];
            float rc[4][4];
            #pragma unroll
            for (int nt = 0; nt < 4; nt++)
                #pragma unroll
                for (int j = 0; j < 4; j++) rc[nt][j] = 0.f;
            #pragma unroll
            for (int nt = 0; nt < 4; nt++) {
                const int n = nrow + nt * 8;
                uint4 B0 = *(const uint4*)&sW2h[n * 36 + cpos * 8];
                uint4 B1 = *(const uint4*)&sW2h[n * 36 + cpos * 8 + 4];
                mma_f16(rc[nt], x00.x, x10.x, x00.y, x10.y, B0.x, B0.y);
                mma_f16(rc[nt], x00.z, x10.z, x00.w, x10.w, B0.z, B0.w);
                mma_f16(rc[nt], x01.x, x11.x, x01.y, x11.y, B1.x, B1.y);
                mma_f16(rc[nt], x01.z, x11.z, x01.w, x11.w, B1.z, B1.w);
            }

            #pragma unroll
            for (int rs = 0; rs < 2; rs++) {
                const int grow = bt + R + rs * 8;
                if (grow == a) continue;   // diagonal mask

                ull rad2[4];
                #pragma unroll
                for (int i = 0; i < 4; i++)
                    rad2[i] = add2(pk2(rc[i][rs * 2], rc[i][rs * 2 + 1]), b2p[i]);

                if (m <= 1) {
                    ulonglong2 Xa = *(const ulonglong2*)&g_x0f[((size_t)(0 + nhalf) * NN + grow) * 16 + cpos * 4];
                    ulonglong2 Xb = *(const ulonglong2*)&g_x0f[((size_t)(2 + nhalf) * NN + grow) * 16 + cpos * 4];
                    ull X[4] = {Xa.x, Xa.y, Xb.x, Xb.y};
                    if (m == 0) {
                        #pragma unroll
                        for (int i = 0; i < 4; i++)
                            acc2[i][0] = fma2(rad2[i], X[i], acc2[i][0]);
                    } else {
                        ulonglong2 Ua = *(const ulonglong2*)&upA[(size_t)grow * 12];
                        ull U2bc = *(const ull*)&upA[(size_t)grow * 12 + 4];
                        #pragma unroll
                        for (int i = 0; i < 4; i++) {
                            ull t = mul2(rad2[i], X[i]);
                            acc2[i][0] = fma2(Ua.x, t, acc2[i][0]);
                            acc2[i][1] = fma2(Ua.y, t, acc2[i][1]);
                            acc2[i][2] = fma2(U2bc, t, acc2[i][2]);
                        }
                    }
                } else {
                    ulonglong2 XXa = *(const ulonglong2*)&g_x1f[((size_t)(0 + nhalf) * NN + grow) * 16 + cpos * 4];
                    ulonglong2 XXb = *(const ulonglong2*)&g_x1f[((size_t)(2 + nhalf) * NN + grow) * 16 + cpos * 4];
                    ulonglong2 XYa = *(const ulonglong2*)&g_x1f[((size_t)(4 + nhalf) * NN + grow) * 16 + cpos * 4];
                    ulonglong2 XYb = *(const ulonglong2*)&g_x1f[((size_t)(6 + nhalf) * NN + grow) * 16 + cpos * 4];
                    ulonglong2 XZa = *(const ulonglong2*)&g_x1f[((size_t)(8 + nhalf) * NN + grow) * 16 + cpos * 4];
                    ulonglong2 XZb = *(const ulonglong2*)&g_x1f[((size_t)(10 + nhalf) * NN + grow) * 16 + cpos * 4];
                    ull XX[4] = {XXa.x, XXa.y, XXb.x, XXb.y};
                    ull XY[4] = {XYa.x, XYa.y, XYb.x, XYb.y};
                    ull XZ[4] = {XZa.x, XZa.y, XZb.x, XZb.y};
                    if (m == 2) {
                        #pragma unroll
                        for (int i = 0; i < 4; i++) {
                            acc2[i][0] = fma2(rad2[i], XX[i], acc2[i][0]);
                            acc2[i][1] = fma2(rad2[i], XY[i], acc2[i][1]);
                            acc2[i][2] = fma2(rad2[i], XZ[i], acc2[i][2]);
                        }
                    } else if (m == 3) {
                        ulonglong2 Ua = *(const ulonglong2*)&upA[(size_t)grow * 12];
                        ull U2bc = *(const ull*)&upA[(size_t)grow * 12 + 4];
                        #pragma unroll
                        for (int i = 0; i < 4; i++) {
                            ull d = mul2(Ua.x, XX[i]);
                            d = fma2(Ua.y, XY[i], d);
                            d = fma2(U2bc, XZ[i], d);
                            acc2[i][0] = fma2(rad2[i], d, acc2[i][0]);
                        }
                    } else {   // m == 4 : cross product u x x1
                        ulonglong2 Ua = *(const ulonglong2*)&upA[(size_t)grow * 12];      // u0,u1
                        ulonglong2 Ub = *(const ulonglong2*)&upA[(size_t)grow * 12 + 4];  // u2,-u0
                        ulonglong2 Uc = *(const ulonglong2*)&upA[(size_t)grow * 12 + 8];  // -u1,-u2
                        #pragma unroll
                        for (int i = 0; i < 4; i++) {
                            ull cx = fma2(Uc.y, XY[i], mul2(Ua.y, XZ[i]));   // u1*xz - u2*xy
                            ull cy = fma2(Ub.y, XZ[i], mul2(Ub.x, XX[i]));   // u2*xx - u0*xz
                            ull cz = fma2(Uc.x, XX[i], mul2(Ua.x, XY[i]));   // u0*xy - u1*xx
                            acc2[i][0] = fma2(rad2[i], cx, acc2[i][0]);
                            acc2[i][1] = fma2(rad2[i], cy, acc2[i][1]);
                            acc2[i][2] = fma2(rad2[i], cz, acc2[i][2]);
                        }
                    }
                }
            }
        }
    }

    // ---- cross-thread reduction (16 contributors per output channel) ----
    __syncthreads();
    float* sPart = smem;   // W1/W2 regions dead; 3072 <= 3328 floats
    {
        const int base = tid * 24;
        #pragma unroll
        for (int i = 0; i < 4; i++)
            #pragma unroll
            for (int c = 0; c < 3; c++) {
                float lo, hi;
                upk2(lo, hi, acc2[i][c]);
                sPart[base + (2 * i) * 3 + c]     = lo;
                sPart[base + (2 * i + 1) * 3 + c] = hi;
            }
    }
    __syncthreads();

    const float nm = rsqrtf((float)(NN - 1));
    float* out1 = out + NN * 2 * CC;

    for (int idx = tid; idx < CC * 3; idx += NT) {
        const int f    = idx / 3;
        const int comp = idx - f * 3;
        const int nh = f >> 5;
        const int cp = (f >> 3) & 3;
        const int q  = f & 7;
        float s = 0.0f;
        #pragma unroll
        for (int mm = 0; mm < 2; mm++) {
            #pragma unroll
            for (int rg = 0; rg < 8; rg++) {
                int tc = (mm * 2 + nh) * 32 + rg * 4 + cp;
                s += sPart[tc * 24 + q * 3 + comp];
            }
        }
        s *= nm;

        if (m == 0)      { if (comp == 0) out[a * 128 + f] = s; }
        else if (m == 1) { out1[a * 576 + f * 3 + comp] = s; }
        else if (m == 2) { out1[a * 576 + (64 + f) * 3 + comp] = s; }
        else if (m == 3) { if (comp == 0) out[a * 128 + 64 + f] = s; }
        else             { out1[a * 576 + (128 + f) * 3 + comp] = s; }
    }
}

extern "C" void kernel_launch(void* const* d_in, const int* in_sizes, int n_in,
                              void* d_out, int out_size) {
    const float* x0  = (const float*)d_in[0];
    const float* x1  = (const float*)d_in[1];
    const float* rbf = (const float*)d_in[2];
    const float* u   = (const float*)d_in[3];
    // d_in[4] = r_ij : unused (switching_fn == None)
    const float* w1  = (const float*)d_in[5];
    const float* b1  = (const float*)d_in[6];
    const float* w2  = (const float*)d_in[7];
    const float* b2  = (const float*)d_in[8];
    float* out = (float*)d_out;

    prep_rbfh_kernel<<<(NN * NN * 4) / 256, 256>>>(rbf);
    prep_misc_kernel<<<(NN * NN * 3 + 4 * NN * 4 + 12 * NN * 4) / 256, 256>>>(x0, x1, u);

    cudaFuncSetAttribute(conv_tfn_h19_kernel,
                         cudaFuncAttributeMaxDynamicSharedMemorySize, SMEM_BYTES);
    dim3 grid(NN, 5);
    conv_tfn_h19_kernel<<<grid, NT, SMEM_BYTES>>>(w1, b1, w2, b2, out);
}